// round 6
// baseline (speedup 1.0000x reference)
#include <cuda_runtime.h>
#include <cuda_bf16.h>
#include <cuda_fp16.h>
#include <stdint.h>

#define NN 50000
#define NNP 50048              // padded to multiple of 128 (GEMM tile rows)
#define NG 256
#define DIM 128
#define NE 800000

typedef __nv_bfloat16 bf16;

// ---------------- scratch (static __device__ => no runtime allocation) ------
__device__ __half g_xf  [NN * DIM];
__device__ __half g_hfA [NN * DIM];
__device__ __half g_hfB [NN * DIM];
__device__ bf16  g_aggHi[NNP * DIM], g_aggLo[NNP * DIM];
__device__ bf16  g_h0Hi [NNP * DIM], g_h0Lo [NNP * DIM];
__device__ bf16  g_h1Hi [NNP * DIM], g_h1Lo [NNP * DIM];
__device__ bf16  g_h2Hi [NNP * DIM], g_h2Lo [NNP * DIM];
__device__ bf16  g_wtHi[6 * DIM * DIM], g_wtLo[6 * DIM * DIM];
__device__ int   g_rowptr[NN + 1];
__device__ int   g_cnt[NN];
__device__ int   g_col[NE];
__device__ int   g_gstart[NG + 1];
__device__ int   g_is64;
__device__ int   g_bsum[256];
__device__ int   g_boff[256];

// ---------------- dtype-agnostic index access -------------------------------
__device__ __forceinline__ long long idx_at(const void* p, long long i) {
    if (g_is64) return ((const long long*)p)[i];
    return (long long)((const int*)p)[i];
}

__device__ __forceinline__ void split2(float a, float b, unsigned& hi, unsigned& lo) {
    bf16 ha = __float2bfloat16_rn(a), hb = __float2bfloat16_rn(b);
    bf16 la = __float2bfloat16_rn(a - __bfloat162float(ha));
    bf16 lb = __float2bfloat16_rn(b - __bfloat162float(hb));
    __nv_bfloat162 h2 = __nv_bfloat162(ha, hb), l2 = __nv_bfloat162(la, lb);
    hi = *(unsigned*)&h2; lo = *(unsigned*)&l2;
}

__device__ __forceinline__ uint32_t smem_u32(const void* p) {
    uint32_t a;
    asm("{ .reg .u64 t; cvta.to.shared.u64 t, %1; cvt.u32.u64 %0, t; }" : "=r"(a) : "l"(p));
    return a;
}

// ---------------- init / detect ----------------------------------------------
__global__ void k_init() {
    int i = blockIdx.x * blockDim.x + threadIdx.x;
    if (i < NN) g_cnt[i] = 0;
    if (i == 0) g_is64 = 1;
}

// Sample first 4096 32-bit words. If edges are int64 (nonneg < 2^31) the odd
// words are all zero; if int32 they are ~2048 random node ids (P(all 0) ~= 0).
__global__ void k_detect(const int* __restrict__ ei32, int e2) {
    int idx = 2 * threadIdx.x + 1;
    for (int k = 0; k < 8; k++, idx += 512)
        if (idx < e2 && idx < 4096 && ei32[idx] != 0) g_is64 = 0;
}

// ---------------- CSR build --------------------------------------------------
__global__ void k_count(const void* __restrict__ ei, int E) {
    int e = blockIdx.x * blockDim.x + threadIdx.x;
    if (e >= E) return;
    int d = (int)idx_at(ei, (long long)E + e);
    atomicAdd(&g_cnt[d], 1);
}

__device__ __forceinline__ int blk_excl_scan(int v, int* warpsum) {
    int tid = threadIdx.x, lane = tid & 31, w = tid >> 5;
    int x = v;
    #pragma unroll
    for (int o = 1; o < 32; o <<= 1) {
        int y = __shfl_up_sync(0xFFFFFFFFu, x, o);
        if (lane >= o) x += y;
    }
    if (lane == 31) warpsum[w] = x;
    __syncthreads();
    if (w == 0 && lane < 8) {
        int s = warpsum[lane];
        #pragma unroll
        for (int o = 1; o < 8; o <<= 1) {
            int y = __shfl_up_sync(0xFFu, s, o);
            if (lane >= o) s += y;
        }
        warpsum[lane] = s;
    }
    __syncthreads();
    return x - v + (w > 0 ? warpsum[w - 1] : 0);
}

__global__ void k_bsum(int n) {
    __shared__ int warpsum[8];
    int i = blockIdx.x * 256 + threadIdx.x;
    int v = (i < n) ? g_cnt[i] : 0;
    int lane = threadIdx.x & 31, w = threadIdx.x >> 5;
    #pragma unroll
    for (int o = 16; o > 0; o >>= 1) v += __shfl_down_sync(0xFFFFFFFFu, v, o);
    if (lane == 0) warpsum[w] = v;
    __syncthreads();
    if (threadIdx.x == 0) {
        int s = 0;
        #pragma unroll
        for (int k = 0; k < 8; k++) s += warpsum[k];
        g_bsum[blockIdx.x] = s;
    }
}

__global__ void k_bscan(int nb, int n) {
    __shared__ int warpsum[8];
    int t = threadIdx.x;
    int v = (t < nb) ? g_bsum[t] : 0;
    int excl = blk_excl_scan(v, warpsum);
    if (t < nb) g_boff[t] = excl;
    if (t == nb - 1) g_rowptr[n] = excl + v;
}

__global__ void k_rowptr(int n) {
    __shared__ int warpsum[8];
    int i = blockIdx.x * 256 + threadIdx.x;
    int v = (i < n) ? g_cnt[i] : 0;
    int excl = blk_excl_scan(v, warpsum);
    if (i < n) { g_rowptr[i] = g_boff[blockIdx.x] + excl; g_cnt[i] = 0; }
}

__global__ void k_fill(const void* __restrict__ ei, int E) {
    int e = blockIdx.x * blockDim.x + threadIdx.x;
    if (e >= E) return;
    int s = (int)idx_at(ei, e);
    int d = (int)idx_at(ei, (long long)E + e);
    int pos = g_rowptr[d] + atomicAdd(&g_cnt[d], 1);
    g_col[pos] = s;
}

// ---------------- prep -------------------------------------------------------
__global__ void k_prepx(const float* __restrict__ x, int n4) {
    int i = blockIdx.x * blockDim.x + threadIdx.x;
    if (i >= n4) return;
    float4 v = *(const float4*)(x + (size_t)i * 4);
    uint2 hi, lo;
    split2(v.x, v.y, hi.x, lo.x);
    split2(v.z, v.w, hi.y, lo.y);
    *(uint2*)(g_h0Hi + (size_t)i * 4) = hi;
    *(uint2*)(g_h0Lo + (size_t)i * 4) = lo;
    __half2 f0 = __floats2half2_rn(v.x, v.y);
    __half2 f1 = __floats2half2_rn(v.z, v.w);
    *(__half2*)(g_xf + (size_t)i * 4)     = f0;
    *(__half2*)(g_xf + (size_t)i * 4 + 2) = f1;
}

// one matrix per blockIdx.y; Wt[m][n][k] = W[m][k][n]
__global__ void k_prepw(const float* __restrict__ W0, const float* __restrict__ W1,
                        const float* __restrict__ W2, const float* __restrict__ W3,
                        const float* __restrict__ W4, const float* __restrict__ W5) {
    const float* Ws[6] = {W0, W1, W2, W3, W4, W5};
    int m = blockIdx.y;
    int i = blockIdx.x * blockDim.x + threadIdx.x;
    if (i >= DIM * DIM) return;
    int n = i >> 7, k = i & 127;
    float v = Ws[m][k * DIM + n];
    bf16 h = __float2bfloat16_rn(v);
    bf16 l = __float2bfloat16_rn(v - __bfloat162float(h));
    g_wtHi[m * DIM * DIM + i] = h;
    g_wtLo[m * DIM * DIM + i] = l;
}

// ---------------- mean aggregation: one warp per node, fp16 gather ----------
__global__ void k_agg(const __half* __restrict__ h, int N) {
    int warp = (blockIdx.x * blockDim.x + threadIdx.x) >> 5;
    int lane = threadIdx.x & 31;
    if (warp >= N) return;
    int beg = g_rowptr[warp], end = g_rowptr[warp + 1];
    float4 acc = make_float4(0.f, 0.f, 0.f, 0.f);
    int i = beg;
    for (; i + 3 < end; i += 4) {
        int s0 = __ldg(&g_col[i]),     s1 = __ldg(&g_col[i + 1]);
        int s2 = __ldg(&g_col[i + 2]), s3 = __ldg(&g_col[i + 3]);
        uint2 v0 = *(const uint2*)(h + (size_t)s0 * DIM + lane * 4);
        uint2 v1 = *(const uint2*)(h + (size_t)s1 * DIM + lane * 4);
        uint2 v2 = *(const uint2*)(h + (size_t)s2 * DIM + lane * 4);
        uint2 v3 = *(const uint2*)(h + (size_t)s3 * DIM + lane * 4);
        float2 a0 = __half22float2(*(__half2*)&v0.x), a1 = __half22float2(*(__half2*)&v0.y);
        float2 b0 = __half22float2(*(__half2*)&v1.x), b1 = __half22float2(*(__half2*)&v1.y);
        float2 c0 = __half22float2(*(__half2*)&v2.x), c1 = __half22float2(*(__half2*)&v2.y);
        float2 d0 = __half22float2(*(__half2*)&v3.x), d1 = __half22float2(*(__half2*)&v3.y);
        acc.x += (a0.x + b0.x) + (c0.x + d0.x);
        acc.y += (a0.y + b0.y) + (c0.y + d0.y);
        acc.z += (a1.x + b1.x) + (c1.x + d1.x);
        acc.w += (a1.y + b1.y) + (c1.y + d1.y);
    }
    for (; i < end; i++) {
        int s0 = __ldg(&g_col[i]);
        uint2 v0 = *(const uint2*)(h + (size_t)s0 * DIM + lane * 4);
        float2 a0 = __half22float2(*(__half2*)&v0.x);
        float2 a1 = __half22float2(*(__half2*)&v0.y);
        acc.x += a0.x; acc.y += a0.y; acc.z += a1.x; acc.w += a1.y;
    }
    int deg = end - beg;
    float inv = 1.0f / (float)(deg > 0 ? deg : 1);
    uint2 hi, lo;
    split2(acc.x * inv, acc.y * inv, hi.x, lo.x);
    split2(acc.z * inv, acc.w * inv, hi.y, lo.y);
    size_t off = (size_t)warp * DIM + lane * 4;
    *(uint2*)(g_aggHi + off) = hi;
    *(uint2*)(g_aggLo + off) = lo;
}

// ---------------- tensor-core fused dual GEMM (ldmatrix fragments) ----------
// out = relu(A@Wl + H@Wr + bias); operands pre-split bf16 hi/lo in global.
// 3-product accumulation: hi*hi + hi*lo + lo*hi  (~1e-5 accuracy).
// BM=128, BN=128; 8 chunks of BK=32 (0-3: A/Wl, 4-7: H/Wr). 8 warps (4x2).
// Fragments loaded via ldmatrix.x4; smem rows 40 bf16 (80B = 5*16B, LDSM-legal,
// conflict-free: bank = 20n mod 32 distinct over any 8 consecutive rows).
__device__ __forceinline__ void mma_bf16(float* c, const unsigned* a, const unsigned* b) {
    asm volatile(
        "mma.sync.aligned.m16n8k16.row.col.f32.bf16.bf16.f32 "
        "{%0,%1,%2,%3}, {%4,%5,%6,%7}, {%8,%9}, {%0,%1,%2,%3};\n"
        : "+f"(c[0]), "+f"(c[1]), "+f"(c[2]), "+f"(c[3])
        : "r"(a[0]), "r"(a[1]), "r"(a[2]), "r"(a[3]), "r"(b[0]), "r"(b[1]));
}
__device__ __forceinline__ void ldsm4(unsigned& r0, unsigned& r1, unsigned& r2, unsigned& r3,
                                      uint32_t addr) {
    asm volatile("ldmatrix.sync.aligned.m8n8.x4.shared.b16 {%0,%1,%2,%3}, [%4];"
                 : "=r"(r0), "=r"(r1), "=r"(r2), "=r"(r3) : "r"(addr));
}

#define LDW 40   // bf16 per smem row (80 bytes)

__global__ void __launch_bounds__(256)
k_gemm_tc(const bf16* __restrict__ Ahi, const bf16* __restrict__ Alo,
          const bf16* __restrict__ Hhi, const bf16* __restrict__ Hlo,
          const bf16* __restrict__ WtHi, const bf16* __restrict__ WtLo,
          const float* __restrict__ bias, __half* __restrict__ outF,
          bf16* __restrict__ outHi, bf16* __restrict__ outLo, int M)
{
    __shared__ __align__(16) bf16 sAhi[128][LDW], sAlo[128][LDW];
    __shared__ __align__(16) bf16 sWhi[128][LDW], sWlo[128][LDW];

    const int tid  = threadIdx.x;
    const int lane = tid & 31, warp = tid >> 5;
    const int wm = warp & 3, wn = warp >> 2;   // 4 x 2 warp grid
    const int g  = lane >> 2, t = lane & 3;
    const int row0 = blockIdx.x * 128;

    // ldmatrix source addresses (byte offsets within a [128][LDW] array):
    // A: row = rm + (lane&15), col = k0 + 8*(lane>>4)
    const uint32_t aRow = (uint32_t)(lane & 15), aKH = (uint32_t)((lane >> 4) * 8);
    // B: row = n0 + (lane&7) + 8*(lane>>4), col = k0 + 8*((lane>>3)&1)
    const uint32_t bRow = (uint32_t)((lane & 7) + 8 * (lane >> 4));
    const uint32_t bKH  = (uint32_t)(((lane >> 3) & 1) * 8);

    const uint32_t sAhiB = smem_u32(sAhi), sAloB = smem_u32(sAlo);
    const uint32_t sWhiB = smem_u32(sWhi), sWloB = smem_u32(sWlo);

    float acc[2][8][4];
    #pragma unroll
    for (int a = 0; a < 2; a++)
        #pragma unroll
        for (int b = 0; b < 8; b++)
            #pragma unroll
            for (int c = 0; c < 4; c++) acc[a][b][c] = 0.f;

    for (int kc = 0; kc < 8; kc++) {
        const bf16* srcHi = (kc < 4) ? Ahi : Hhi;
        const bf16* srcLo = (kc < 4) ? Alo : Hlo;
        const bf16* wHi   = WtHi + ((kc < 4) ? 0 : DIM * DIM);
        const bf16* wLo   = WtLo + ((kc < 4) ? 0 : DIM * DIM);
        const int koff = (kc & 3) * 32;

        // fill tiles: 128 rows x 32 k each; 512 uint4 per array, 2 per thread
        #pragma unroll
        for (int j = 0; j < 2; j++) {
            int i = tid + j * 256;
            int r = i >> 2, k8 = (i & 3) * 8;
            size_t ga = (size_t)(row0 + r) * DIM + koff + k8;   // padded, in-bounds
            size_t gw = (size_t)r * DIM + koff + k8;
            *(uint4*)&sAhi[r][k8] = *(const uint4*)(srcHi + ga);
            *(uint4*)&sAlo[r][k8] = *(const uint4*)(srcLo + ga);
            *(uint4*)&sWhi[r][k8] = *(const uint4*)(wHi + gw);
            *(uint4*)&sWlo[r][k8] = *(const uint4*)(wLo + gw);
        }
        __syncthreads();

        #pragma unroll
        for (int k0 = 0; k0 < 32; k0 += 16) {
            unsigned ahi[2][4], alo[2][4];
            #pragma unroll
            for (int mt = 0; mt < 2; mt++) {
                uint32_t off = ((uint32_t)(wm * 32 + mt * 16) + aRow) * (LDW * 2)
                             + (k0 + aKH) * 2;
                ldsm4(ahi[mt][0], ahi[mt][1], ahi[mt][2], ahi[mt][3], sAhiB + off);
                ldsm4(alo[mt][0], alo[mt][1], alo[mt][2], alo[mt][3], sAloB + off);
            }
            #pragma unroll
            for (int np = 0; np < 4; np++) {       // n-pairs of 16 cols
                uint32_t off = ((uint32_t)(wn * 64 + np * 16) + bRow) * (LDW * 2)
                             + (k0 + bKH) * 2;
                unsigned bh[4], bl[4];
                ldsm4(bh[0], bh[1], bh[2], bh[3], sWhiB + off);
                ldsm4(bl[0], bl[1], bl[2], bl[3], sWloB + off);
                #pragma unroll
                for (int half = 0; half < 2; half++) {   // nt = 2*np + half
                    int nt = 2 * np + half;
                    unsigned* bhp = bh + 2 * half;
                    unsigned* blp = bl + 2 * half;
                    #pragma unroll
                    for (int mt = 0; mt < 2; mt++) {
                        mma_bf16(acc[mt][nt], ahi[mt], bhp);
                        mma_bf16(acc[mt][nt], ahi[mt], blp);
                        mma_bf16(acc[mt][nt], alo[mt], bhp);
                    }
                }
            }
        }
        __syncthreads();
    }

    // epilogue: + bias, relu; store fp16 + bf16 hi/lo
    #pragma unroll
    for (int mt = 0; mt < 2; mt++) {
        int r0 = row0 + wm * 32 + mt * 16 + g;
        #pragma unroll
        for (int nt = 0; nt < 8; nt++) {
            int c = wn * 64 + nt * 8 + 2 * t;
            float b0 = __ldg(bias + c), b1 = __ldg(bias + c + 1);
            #pragma unroll
            for (int half = 0; half < 2; half++) {
                int rr = r0 + half * 8;
                if (rr < M) {
                    float ox = fmaxf(acc[mt][nt][2 * half]     + b0, 0.f);
                    float oy = fmaxf(acc[mt][nt][2 * half + 1] + b1, 0.f);
                    size_t off = (size_t)rr * DIM + c;
                    *(__half2*)(outF + off) = __floats2half2_rn(ox, oy);
                    unsigned hi, lo;
                    split2(ox, oy, hi, lo);
                    *(unsigned*)(outHi + off) = hi;
                    *(unsigned*)(outLo + off) = lo;
                }
            }
        }
    }
}

// ---------------- per-graph boundaries (batch is sorted) --------------------
__global__ void k_bounds(const void* __restrict__ batch, int n) {
    int g = blockIdx.x * blockDim.x + threadIdx.x;
    if (g > NG) return;
    int lo = 0, hi = n;
    while (lo < hi) {
        int mid = (lo + hi) >> 1;
        if (idx_at(batch, mid) < (long long)g) lo = mid + 1; else hi = mid;
    }
    g_gstart[g] = lo;
}

// ---------------- meanmax readout: one block per graph, fp16 input ----------
__global__ void k_readout(const __half* __restrict__ h, float* __restrict__ out) {
    int g = blockIdx.x;
    int c = threadIdx.x;                 // 0..127
    int s = g_gstart[g], e = g_gstart[g + 1];
    float sum = 0.f, mx = 0.f;           // post-relu values >= 0; empty -> 0
    for (int n = s; n < e; n++) {
        float v = __half2float(__ldg(h + (size_t)n * DIM + c));
        sum += v;
        mx = fmaxf(mx, v);
    }
    out[g * (2 * DIM) + c]       = sum / fmaxf((float)(e - s), 1.f);
    out[g * (2 * DIM) + DIM + c] = mx;
}

// ---------------- launcher ---------------------------------------------------
extern "C" void kernel_launch(void* const* d_in, const int* in_sizes, int n_in,
                              void* d_out, int out_size)
{
    const float* x     = (const float*)d_in[0];
    const void*  ei    = d_in[1];
    const void*  batch = d_in[2];
    const float* Wl0 = (const float*)d_in[3];
    const float* bl0 = (const float*)d_in[4];
    const float* Wr0 = (const float*)d_in[5];
    const float* Wl1 = (const float*)d_in[6];
    const float* bl1 = (const float*)d_in[7];
    const float* Wr1 = (const float*)d_in[8];
    const float* Wl2 = (const float*)d_in[9];
    const float* bl2 = (const float*)d_in[10];
    const float* Wr2 = (const float*)d_in[11];
    float* out = (float*)d_out;

    const int N = in_sizes[0] / DIM;     // 50000
    const int E = in_sizes[1] / 2;       // 800000

    __half *xf, *hfA, *hfB;
    bf16 *aggHi, *aggLo, *h0Hi, *h0Lo, *h1Hi, *h1Lo, *h2Hi, *h2Lo, *wtHi, *wtLo;
    cudaGetSymbolAddress((void**)&xf,  g_xf);
    cudaGetSymbolAddress((void**)&hfA, g_hfA);
    cudaGetSymbolAddress((void**)&hfB, g_hfB);
    cudaGetSymbolAddress((void**)&aggHi, g_aggHi);
    cudaGetSymbolAddress((void**)&aggLo, g_aggLo);
    cudaGetSymbolAddress((void**)&h0Hi, g_h0Hi);
    cudaGetSymbolAddress((void**)&h0Lo, g_h0Lo);
    cudaGetSymbolAddress((void**)&h1Hi, g_h1Hi);
    cudaGetSymbolAddress((void**)&h1Lo, g_h1Lo);
    cudaGetSymbolAddress((void**)&h2Hi, g_h2Hi);
    cudaGetSymbolAddress((void**)&h2Lo, g_h2Lo);
    cudaGetSymbolAddress((void**)&wtHi, g_wtHi);
    cudaGetSymbolAddress((void**)&wtLo, g_wtLo);

    const int nb = (N + 255) / 256;

    k_init  <<<(NN + 255) / 256, 256>>>();
    k_detect<<<1, 256>>>((const int*)ei, 2 * E);
    k_count <<<(E + 255) / 256, 256>>>(ei, E);
    k_bsum  <<<nb, 256>>>(N);
    k_bscan <<<1, 256>>>(nb, N);
    k_rowptr<<<nb, 256>>>(N);
    k_fill  <<<(E + 255) / 256, 256>>>(ei, E);

    k_prepx <<<(N * 32 + 255) / 256, 256>>>(x, N * 32);
    {
        dim3 gw((DIM * DIM + 255) / 256, 6);
        k_prepw<<<gw, 256>>>(Wl0, Wr0, Wl1, Wr1, Wl2, Wr2);
    }

    const int aggGrid  = (N * 32 + 255) / 256;
    const int gemmGrid = (N + 127) / 128;

    // layer 0
    k_agg    <<<aggGrid, 256>>>(xf, N);
    k_gemm_tc<<<gemmGrid, 256>>>(aggHi, aggLo, h0Hi, h0Lo,
                                 wtHi + 0 * DIM * DIM, wtLo + 0 * DIM * DIM,
                                 bl0, hfA, h1Hi, h1Lo, N);
    // layer 1
    k_agg    <<<aggGrid, 256>>>(hfA, N);
    k_gemm_tc<<<gemmGrid, 256>>>(aggHi, aggLo, h1Hi, h1Lo,
                                 wtHi + 2 * DIM * DIM, wtLo + 2 * DIM * DIM,
                                 bl1, hfB, h2Hi, h2Lo, N);
    // layer 2
    k_agg    <<<aggGrid, 256>>>(hfB, N);
    k_gemm_tc<<<gemmGrid, 256>>>(aggHi, aggLo, h2Hi, h2Lo,
                                 wtHi + 4 * DIM * DIM, wtLo + 4 * DIM * DIM,
                                 bl2, hfA, h1Hi, h1Lo, N);

    k_bounds <<<1, 512>>>(batch, N);
    k_readout<<<NG, DIM>>>(hfA, out);
}

// round 7
// speedup vs baseline: 1.2676x; 1.2676x over previous
#include <cuda_runtime.h>
#include <cuda_bf16.h>
#include <cuda_fp16.h>
#include <stdint.h>

#define NN 50000
#define NNP 50048              // padded to 391*128 (GEMM tile rows)
#define NG 256
#define DIM 128
#define NE 800000

typedef __nv_bfloat16 bf16;

// ---------------- scratch (static __device__ => no runtime allocation) ------
__device__ __half g_xf  [NN * DIM];
__device__ __half g_hfA [NN * DIM];
__device__ __half g_hfB [NN * DIM];
__device__ bf16  g_aggHi[NNP * DIM], g_aggLo[NNP * DIM];
__device__ bf16  g_h0Hi [NNP * DIM], g_h0Lo [NNP * DIM];
__device__ bf16  g_h1Hi [NNP * DIM], g_h1Lo [NNP * DIM];
__device__ bf16  g_h2Hi [NNP * DIM], g_h2Lo [NNP * DIM];
__device__ bf16  g_wtHi[6 * DIM * DIM], g_wtLo[6 * DIM * DIM];
__device__ int   g_rowptr[NN + 1];
__device__ int   g_cnt[NN];
__device__ int   g_col[NE];
__device__ int   g_gstart[NG + 1];
__device__ int   g_is64;
__device__ int   g_bsum[256];
__device__ int   g_boff[256];

// ---------------- helpers ----------------------------------------------------
__device__ __forceinline__ long long idx_at(const void* p, long long i) {
    if (g_is64) return ((const long long*)p)[i];
    return (long long)((const int*)p)[i];
}

__device__ __forceinline__ void split2(float a, float b, unsigned& hi, unsigned& lo) {
    bf16 ha = __float2bfloat16_rn(a), hb = __float2bfloat16_rn(b);
    bf16 la = __float2bfloat16_rn(a - __bfloat162float(ha));
    bf16 lb = __float2bfloat16_rn(b - __bfloat162float(hb));
    __nv_bfloat162 h2 = __nv_bfloat162(ha, hb), l2 = __nv_bfloat162(la, lb);
    hi = *(unsigned*)&h2; lo = *(unsigned*)&l2;
}

__device__ __forceinline__ uint32_t smem_u32(const void* p) {
    uint32_t a;
    asm("{ .reg .u64 t; cvta.to.shared.u64 t, %1; cvt.u32.u64 %0, t; }" : "=r"(a) : "l"(p));
    return a;
}

__device__ __forceinline__ void cpa16(uint32_t dst, const void* src) {
    asm volatile("cp.async.ca.shared.global [%0], [%1], 16;" :: "r"(dst), "l"(src) : "memory");
}
__device__ __forceinline__ void cpa_commit() {
    asm volatile("cp.async.commit_group;" ::: "memory");
}
template <int N_>
__device__ __forceinline__ void cpa_wait() {
    asm volatile("cp.async.wait_group %0;" :: "n"(N_) : "memory");
}

// ---------------- init / detect ----------------------------------------------
__global__ void k_init() {
    int i = blockIdx.x * blockDim.x + threadIdx.x;
    if (i < NN) g_cnt[i] = 0;
    if (i == 0) g_is64 = 1;
}

__global__ void k_detect(const int* __restrict__ ei32, int e2) {
    int idx = 2 * threadIdx.x + 1;
    for (int k = 0; k < 8; k++, idx += 512)
        if (idx < e2 && idx < 4096 && ei32[idx] != 0) g_is64 = 0;
}

// ---------------- CSR build --------------------------------------------------
__global__ void k_count(const void* __restrict__ ei, int E) {
    int e = blockIdx.x * blockDim.x + threadIdx.x;
    if (e >= E) return;
    int d = (int)idx_at(ei, (long long)E + e);
    atomicAdd(&g_cnt[d], 1);
}

__device__ __forceinline__ int blk_excl_scan(int v, int* warpsum) {
    int tid = threadIdx.x, lane = tid & 31, w = tid >> 5;
    int x = v;
    #pragma unroll
    for (int o = 1; o < 32; o <<= 1) {
        int y = __shfl_up_sync(0xFFFFFFFFu, x, o);
        if (lane >= o) x += y;
    }
    if (lane == 31) warpsum[w] = x;
    __syncthreads();
    if (w == 0 && lane < 8) {
        int s = warpsum[lane];
        #pragma unroll
        for (int o = 1; o < 8; o <<= 1) {
            int y = __shfl_up_sync(0xFFu, s, o);
            if (lane >= o) s += y;
        }
        warpsum[lane] = s;
    }
    __syncthreads();
    return x - v + (w > 0 ? warpsum[w - 1] : 0);
}

__global__ void k_bsum(int n) {
    __shared__ int warpsum[8];
    int i = blockIdx.x * 256 + threadIdx.x;
    int v = (i < n) ? g_cnt[i] : 0;
    int lane = threadIdx.x & 31, w = threadIdx.x >> 5;
    #pragma unroll
    for (int o = 16; o > 0; o >>= 1) v += __shfl_down_sync(0xFFFFFFFFu, v, o);
    if (lane == 0) warpsum[w] = v;
    __syncthreads();
    if (threadIdx.x == 0) {
        int s = 0;
        #pragma unroll
        for (int k = 0; k < 8; k++) s += warpsum[k];
        g_bsum[blockIdx.x] = s;
    }
}

__global__ void k_bscan(int nb, int n) {
    __shared__ int warpsum[8];
    int t = threadIdx.x;
    int v = (t < nb) ? g_bsum[t] : 0;
    int excl = blk_excl_scan(v, warpsum);
    if (t < nb) g_boff[t] = excl;
    if (t == nb - 1) g_rowptr[n] = excl + v;
}

__global__ void k_rowptr(int n) {
    __shared__ int warpsum[8];
    int i = blockIdx.x * 256 + threadIdx.x;
    int v = (i < n) ? g_cnt[i] : 0;
    int excl = blk_excl_scan(v, warpsum);
    if (i < n) { g_rowptr[i] = g_boff[blockIdx.x] + excl; g_cnt[i] = 0; }
}

__global__ void k_fill(const void* __restrict__ ei, int E) {
    int e = blockIdx.x * blockDim.x + threadIdx.x;
    if (e >= E) return;
    int s = (int)idx_at(ei, e);
    int d = (int)idx_at(ei, (long long)E + e);
    int pos = g_rowptr[d] + atomicAdd(&g_cnt[d], 1);
    g_col[pos] = s;
}

// ---------------- prep -------------------------------------------------------
__global__ void k_prepx(const float* __restrict__ x, int n4) {
    int i = blockIdx.x * blockDim.x + threadIdx.x;
    if (i >= n4) return;
    float4 v = *(const float4*)(x + (size_t)i * 4);
    uint2 hi, lo;
    split2(v.x, v.y, hi.x, lo.x);
    split2(v.z, v.w, hi.y, lo.y);
    *(uint2*)(g_h0Hi + (size_t)i * 4) = hi;
    *(uint2*)(g_h0Lo + (size_t)i * 4) = lo;
    __half2 f0 = __floats2half2_rn(v.x, v.y);
    __half2 f1 = __floats2half2_rn(v.z, v.w);
    *(__half2*)(g_xf + (size_t)i * 4)     = f0;
    *(__half2*)(g_xf + (size_t)i * 4 + 2) = f1;
}

__global__ void k_prepw(const float* __restrict__ W0, const float* __restrict__ W1,
                        const float* __restrict__ W2, const float* __restrict__ W3,
                        const float* __restrict__ W4, const float* __restrict__ W5) {
    const float* Ws[6] = {W0, W1, W2, W3, W4, W5};
    int m = blockIdx.y;
    int i = blockIdx.x * blockDim.x + threadIdx.x;
    if (i >= DIM * DIM) return;
    int n = i >> 7, k = i & 127;
    float v = Ws[m][k * DIM + n];
    bf16 h = __float2bfloat16_rn(v);
    bf16 l = __float2bfloat16_rn(v - __bfloat162float(h));
    g_wtHi[m * DIM * DIM + i] = h;
    g_wtLo[m * DIM * DIM + i] = l;
}

// ---------------- mean aggregation: one warp per node, fp16 gather ----------
__global__ void k_agg(const __half* __restrict__ h, int N) {
    int warp = (blockIdx.x * blockDim.x + threadIdx.x) >> 5;
    int lane = threadIdx.x & 31;
    if (warp >= N) return;
    int beg = g_rowptr[warp], end = g_rowptr[warp + 1];
    float4 acc = make_float4(0.f, 0.f, 0.f, 0.f);
    int i = beg;
    for (; i + 1 < end; i += 2) {
        int s0 = __ldg(&g_col[i]), s1 = __ldg(&g_col[i + 1]);
        uint2 v0 = *(const uint2*)(h + (size_t)s0 * DIM + lane * 4);
        uint2 v1 = *(const uint2*)(h + (size_t)s1 * DIM + lane * 4);
        float2 a0 = __half22float2(*(__half2*)&v0.x);
        float2 a1 = __half22float2(*(__half2*)&v0.y);
        float2 b0 = __half22float2(*(__half2*)&v1.x);
        float2 b1 = __half22float2(*(__half2*)&v1.y);
        acc.x += a0.x + b0.x; acc.y += a0.y + b0.y;
        acc.z += a1.x + b1.x; acc.w += a1.y + b1.y;
    }
    if (i < end) {
        int s0 = __ldg(&g_col[i]);
        uint2 v0 = *(const uint2*)(h + (size_t)s0 * DIM + lane * 4);
        float2 a0 = __half22float2(*(__half2*)&v0.x);
        float2 a1 = __half22float2(*(__half2*)&v0.y);
        acc.x += a0.x; acc.y += a0.y; acc.z += a1.x; acc.w += a1.y;
    }
    int deg = end - beg;
    float inv = 1.0f / (float)(deg > 0 ? deg : 1);
    uint2 hi, lo;
    split2(acc.x * inv, acc.y * inv, hi.x, lo.x);
    split2(acc.z * inv, acc.w * inv, hi.y, lo.y);
    size_t off = (size_t)warp * DIM + lane * 4;
    *(uint2*)(g_aggHi + off) = hi;
    *(uint2*)(g_aggLo + off) = lo;
}

// ---------------- tensor-core fused dual GEMM (cp.async 2-stage) ------------
// out = relu(A@Wl + H@Wr + bias); operands pre-split bf16 hi/lo in global.
// 3-product accumulation: hi*hi + hi*lo + lo*hi  (~1e-5 accuracy).
// BM=128, BN=128; 8 chunks of BK=32 (0-3: A/Wl, 4-7: H/Wr). 8 warps (4x2).
// Fragment loads: R4-style scalar LDS; smem rows 40 bf16 (80B, cp.async-16
// aligned; fragment bank = 20r mod 32, conflict-free over 8 rows).
__device__ __forceinline__ void mma_bf16(float* c, const unsigned* a, const unsigned* b) {
    asm volatile(
        "mma.sync.aligned.m16n8k16.row.col.f32.bf16.bf16.f32 "
        "{%0,%1,%2,%3}, {%4,%5,%6,%7}, {%8,%9}, {%0,%1,%2,%3};\n"
        : "+f"(c[0]), "+f"(c[1]), "+f"(c[2]), "+f"(c[3])
        : "r"(a[0]), "r"(a[1]), "r"(a[2]), "r"(a[3]), "r"(b[0]), "r"(b[1]));
}

#define LDW 40                       // bf16 per smem row (80 B)
#define ARR_B (128 * LDW * 2)        // 10240 B per array
#define STG_B (4 * ARR_B)            // 40960 B per stage
#define GSMEM (2 * STG_B)            // 81920 B total

__global__ void __launch_bounds__(256)
k_gemm_tc(const bf16* __restrict__ Ahi, const bf16* __restrict__ Alo,
          const bf16* __restrict__ Hhi, const bf16* __restrict__ Hlo,
          const bf16* __restrict__ WtHi, const bf16* __restrict__ WtLo,
          const float* __restrict__ bias, __half* __restrict__ outF,
          bf16* __restrict__ outHi, bf16* __restrict__ outLo, int M)
{
    extern __shared__ __align__(16) char smem[];
    const uint32_t sb = smem_u32(smem);

    const int tid  = threadIdx.x;
    const int lane = tid & 31, warp = tid >> 5;
    const int wm = warp & 3, wn = warp >> 2;   // 4 x 2 warp grid
    const int g  = lane >> 2, t = lane & 3;
    const int row0 = blockIdx.x * 128;

    // per-thread load slots: i = tid + j*256, j in {0,1}
    const int r_ld  = tid >> 2;          // rows 0..63 (j=0), 64..127 (j=1)
    const int k8_ld = (tid & 3) * 8;     // k offset 0/8/16/24

    float acc[2][8][4];
    #pragma unroll
    for (int a = 0; a < 2; a++)
        #pragma unroll
        for (int b = 0; b < 8; b++)
            #pragma unroll
            for (int c = 0; c < 4; c++) acc[a][b][c] = 0.f;

    // issue all 8 cp.async for one chunk into one stage
    auto issue = [&](int kc, int stg) {
        const bf16* srcHi = (kc < 4) ? Ahi : Hhi;
        const bf16* srcLo = (kc < 4) ? Alo : Hlo;
        const bf16* wHi   = WtHi + ((kc < 4) ? 0 : DIM * DIM);
        const bf16* wLo   = WtLo + ((kc < 4) ? 0 : DIM * DIM);
        const int koff = (kc & 3) * 32;
        const uint32_t base = sb + stg * STG_B;
        #pragma unroll
        for (int j = 0; j < 2; j++) {
            int r = r_ld + j * 64;
            uint32_t d = base + (uint32_t)(r * LDW + k8_ld) * 2;
            size_t ga = (size_t)(row0 + r) * DIM + koff + k8_ld;  // padded, in-bounds
            size_t gw = (size_t)r * DIM + koff + k8_ld;
            cpa16(d,             srcHi + ga);
            cpa16(d + ARR_B,     srcLo + ga);
            cpa16(d + 2 * ARR_B, wHi + gw);
            cpa16(d + 3 * ARR_B, wLo + gw);
        }
        cpa_commit();
    };

    issue(0, 0);

    for (int kc = 0; kc < 8; kc++) {
        if (kc + 1 < 8) {
            issue(kc + 1, (kc + 1) & 1);
            cpa_wait<1>();
        } else {
            cpa_wait<0>();
        }
        __syncthreads();

        const char* stgp = smem + (kc & 1) * STG_B;
        const bf16 (*sAhi)[LDW] = (const bf16(*)[LDW])(stgp);
        const bf16 (*sAlo)[LDW] = (const bf16(*)[LDW])(stgp + ARR_B);
        const bf16 (*sWhi)[LDW] = (const bf16(*)[LDW])(stgp + 2 * ARR_B);
        const bf16 (*sWlo)[LDW] = (const bf16(*)[LDW])(stgp + 3 * ARR_B);

        #pragma unroll
        for (int k0 = 0; k0 < 32; k0 += 16) {
            unsigned ahi[2][4], alo[2][4];
            #pragma unroll
            for (int mt = 0; mt < 2; mt++) {
                int rm = wm * 32 + mt * 16;
                ahi[mt][0] = *(const unsigned*)&sAhi[rm + g    ][k0 + 2 * t];
                ahi[mt][1] = *(const unsigned*)&sAhi[rm + 8 + g][k0 + 2 * t];
                ahi[mt][2] = *(const unsigned*)&sAhi[rm + g    ][k0 + 2 * t + 8];
                ahi[mt][3] = *(const unsigned*)&sAhi[rm + 8 + g][k0 + 2 * t + 8];
                alo[mt][0] = *(const unsigned*)&sAlo[rm + g    ][k0 + 2 * t];
                alo[mt][1] = *(const unsigned*)&sAlo[rm + 8 + g][k0 + 2 * t];
                alo[mt][2] = *(const unsigned*)&sAlo[rm + g    ][k0 + 2 * t + 8];
                alo[mt][3] = *(const unsigned*)&sAlo[rm + 8 + g][k0 + 2 * t + 8];
            }
            #pragma unroll
            for (int nt = 0; nt < 8; nt++) {
                int cn = wn * 64 + nt * 8 + g;
                unsigned bhi[2], blo[2];
                bhi[0] = *(const unsigned*)&sWhi[cn][k0 + 2 * t];
                bhi[1] = *(const unsigned*)&sWhi[cn][k0 + 2 * t + 8];
                blo[0] = *(const unsigned*)&sWlo[cn][k0 + 2 * t];
                blo[1] = *(const unsigned*)&sWlo[cn][k0 + 2 * t + 8];
                #pragma unroll
                for (int mt = 0; mt < 2; mt++) {
                    mma_bf16(acc[mt][nt], ahi[mt], bhi);
                    mma_bf16(acc[mt][nt], ahi[mt], blo);
                    mma_bf16(acc[mt][nt], alo[mt], bhi);
                }
            }
        }
        __syncthreads();
    }

    // epilogue: + bias, relu; store fp16 + bf16 hi/lo
    #pragma unroll
    for (int mt = 0; mt < 2; mt++) {
        int r0 = row0 + wm * 32 + mt * 16 + g;
        #pragma unroll
        for (int nt = 0; nt < 8; nt++) {
            int c = wn * 64 + nt * 8 + 2 * t;
            float b0 = __ldg(bias + c), b1 = __ldg(bias + c + 1);
            #pragma unroll
            for (int half = 0; half < 2; half++) {
                int rr = r0 + half * 8;
                if (rr < M) {
                    float ox = fmaxf(acc[mt][nt][2 * half]     + b0, 0.f);
                    float oy = fmaxf(acc[mt][nt][2 * half + 1] + b1, 0.f);
                    size_t off = (size_t)rr * DIM + c;
                    *(__half2*)(outF + off) = __floats2half2_rn(ox, oy);
                    unsigned hi, lo;
                    split2(ox, oy, hi, lo);
                    *(unsigned*)(outHi + off) = hi;
                    *(unsigned*)(outLo + off) = lo;
                }
            }
        }
    }
}

// ---------------- per-graph boundaries (batch is sorted) --------------------
__global__ void k_bounds(const void* __restrict__ batch, int n) {
    int g = blockIdx.x * blockDim.x + threadIdx.x;
    if (g > NG) return;
    int lo = 0, hi = n;
    while (lo < hi) {
        int mid = (lo + hi) >> 1;
        if (idx_at(batch, mid) < (long long)g) lo = mid + 1; else hi = mid;
    }
    g_gstart[g] = lo;
}

// ---------------- meanmax readout: one block per graph, fp16 input ----------
__global__ void k_readout(const __half* __restrict__ h, float* __restrict__ out) {
    int g = blockIdx.x;
    int c = threadIdx.x;                 // 0..127
    int s = g_gstart[g], e = g_gstart[g + 1];
    float sum = 0.f, mx = 0.f;           // post-relu values >= 0; empty -> 0
    for (int n = s; n < e; n++) {
        float v = __half2float(__ldg(h + (size_t)n * DIM + c));
        sum += v;
        mx = fmaxf(mx, v);
    }
    out[g * (2 * DIM) + c]       = sum / fmaxf((float)(e - s), 1.f);
    out[g * (2 * DIM) + DIM + c] = mx;
}

// ---------------- launcher ---------------------------------------------------
extern "C" void kernel_launch(void* const* d_in, const int* in_sizes, int n_in,
                              void* d_out, int out_size)
{
    const float* x     = (const float*)d_in[0];
    const void*  ei    = d_in[1];
    const void*  batch = d_in[2];
    const float* Wl0 = (const float*)d_in[3];
    const float* bl0 = (const float*)d_in[4];
    const float* Wr0 = (const float*)d_in[5];
    const float* Wl1 = (const float*)d_in[6];
    const float* bl1 = (const float*)d_in[7];
    const float* Wr1 = (const float*)d_in[8];
    const float* Wl2 = (const float*)d_in[9];
    const float* bl2 = (const float*)d_in[10];
    const float* Wr2 = (const float*)d_in[11];
    float* out = (float*)d_out;

    const int N = in_sizes[0] / DIM;     // 50000
    const int E = in_sizes[1] / 2;       // 800000

    __half *xf, *hfA, *hfB;
    bf16 *aggHi, *aggLo, *h0Hi, *h0Lo, *h1Hi, *h1Lo, *h2Hi, *h2Lo, *wtHi, *wtLo;
    cudaGetSymbolAddress((void**)&xf,  g_xf);
    cudaGetSymbolAddress((void**)&hfA, g_hfA);
    cudaGetSymbolAddress((void**)&hfB, g_hfB);
    cudaGetSymbolAddress((void**)&aggHi, g_aggHi);
    cudaGetSymbolAddress((void**)&aggLo, g_aggLo);
    cudaGetSymbolAddress((void**)&h0Hi, g_h0Hi);
    cudaGetSymbolAddress((void**)&h0Lo, g_h0Lo);
    cudaGetSymbolAddress((void**)&h1Hi, g_h1Hi);
    cudaGetSymbolAddress((void**)&h1Lo, g_h1Lo);
    cudaGetSymbolAddress((void**)&h2Hi, g_h2Hi);
    cudaGetSymbolAddress((void**)&h2Lo, g_h2Lo);
    cudaGetSymbolAddress((void**)&wtHi, g_wtHi);
    cudaGetSymbolAddress((void**)&wtLo, g_wtLo);

    cudaFuncSetAttribute(k_gemm_tc, cudaFuncAttributeMaxDynamicSharedMemorySize, GSMEM);

    const int nb = (N + 255) / 256;

    k_init  <<<(NN + 255) / 256, 256>>>();
    k_detect<<<1, 256>>>((const int*)ei, 2 * E);
    k_count <<<(E + 255) / 256, 256>>>(ei, E);
    k_bsum  <<<nb, 256>>>(N);
    k_bscan <<<1, 256>>>(nb, N);
    k_rowptr<<<nb, 256>>>(N);
    k_fill  <<<(E + 255) / 256, 256>>>(ei, E);

    k_prepx <<<(N * 32 + 255) / 256, 256>>>(x, N * 32);
    {
        dim3 gw((DIM * DIM + 255) / 256, 6);
        k_prepw<<<gw, 256>>>(Wl0, Wr0, Wl1, Wr1, Wl2, Wr2);
    }

    const int aggGrid  = (N * 32 + 255) / 256;
    const int gemmGrid = (N + 127) / 128;

    // layer 0
    k_agg    <<<aggGrid, 256>>>(xf, N);
    k_gemm_tc<<<gemmGrid, 256, GSMEM>>>(aggHi, aggLo, h0Hi, h0Lo,
                                        wtHi + 0 * DIM * DIM, wtLo + 0 * DIM * DIM,
                                        bl0, hfA, h1Hi, h1Lo, N);
    // layer 1
    k_agg    <<<aggGrid, 256>>>(hfA, N);
    k_gemm_tc<<<gemmGrid, 256, GSMEM>>>(aggHi, aggLo, h1Hi, h1Lo,
                                        wtHi + 2 * DIM * DIM, wtLo + 2 * DIM * DIM,
                                        bl1, hfB, h2Hi, h2Lo, N);
    // layer 2
    k_agg    <<<aggGrid, 256>>>(hfB, N);
    k_gemm_tc<<<gemmGrid, 256, GSMEM>>>(aggHi, aggLo, h2Hi, h2Lo,
                                        wtHi + 4 * DIM * DIM, wtLo + 4 * DIM * DIM,
                                        bl2, hfA, h1Hi, h1Lo, N);

    k_bounds <<<1, 512>>>(batch, N);
    k_readout<<<NG, DIM>>>(hfA, out);
}

// round 8
// speedup vs baseline: 1.3107x; 1.0340x over previous
#include <cuda_runtime.h>
#include <cuda_bf16.h>
#include <cuda_fp16.h>
#include <stdint.h>

#define NN 50000
#define NNP 50048              // padded to 391*128 (GEMM tile rows)
#define NG 256
#define DIM 128
#define NE 800000

typedef __nv_bfloat16 bf16;

// ---------------- scratch (static __device__ => no runtime allocation) ------
__device__ __half g_xf  [NN * DIM];
__device__ __half g_hfA [NN * DIM];
__device__ __half g_hfB [NN * DIM];
__device__ bf16  g_aggHi[NNP * DIM], g_aggLo[NNP * DIM];
__device__ bf16  g_h0Hi [NNP * DIM], g_h0Lo [NNP * DIM];
__device__ bf16  g_h1Hi [NNP * DIM], g_h1Lo [NNP * DIM];
__device__ bf16  g_h2Hi [NNP * DIM], g_h2Lo [NNP * DIM];
__device__ bf16  g_wtHi[6 * DIM * DIM], g_wtLo[6 * DIM * DIM];
__device__ int   g_rowptr[NN + 1];
__device__ int   g_cnt[NN];
__device__ int   g_col[NE];
__device__ int   g_is64;
__device__ int   g_bsum[256];

// ---------------- helpers ----------------------------------------------------
__device__ __forceinline__ long long idx_at(const void* p, long long i) {
    if (g_is64) return ((const long long*)p)[i];
    return (long long)((const int*)p)[i];
}

__device__ __forceinline__ void split2(float a, float b, unsigned& hi, unsigned& lo) {
    bf16 ha = __float2bfloat16_rn(a), hb = __float2bfloat16_rn(b);
    bf16 la = __float2bfloat16_rn(a - __bfloat162float(ha));
    bf16 lb = __float2bfloat16_rn(b - __bfloat162float(hb));
    __nv_bfloat162 h2 = __nv_bfloat162(ha, hb), l2 = __nv_bfloat162(la, lb);
    hi = *(unsigned*)&h2; lo = *(unsigned*)&l2;
}

__device__ __forceinline__ uint32_t smem_u32(const void* p) {
    uint32_t a;
    asm("{ .reg .u64 t; cvta.to.shared.u64 t, %1; cvt.u32.u64 %0, t; }" : "=r"(a) : "l"(p));
    return a;
}

__device__ __forceinline__ void cpa16(uint32_t dst, const void* src) {
    asm volatile("cp.async.ca.shared.global [%0], [%1], 16;" :: "r"(dst), "l"(src) : "memory");
}
__device__ __forceinline__ void cpa_commit() {
    asm volatile("cp.async.commit_group;" ::: "memory");
}
template <int N_>
__device__ __forceinline__ void cpa_wait() {
    asm volatile("cp.async.wait_group %0;" :: "n"(N_) : "memory");
}

// ---------------- init / detect ----------------------------------------------
__global__ void k_init() {
    int i = blockIdx.x * blockDim.x + threadIdx.x;
    if (i < NN) g_cnt[i] = 0;
    if (i == 0) g_is64 = 1;
}

// Sample first 4096 32-bit words. If edges are int64 (nonneg < 2^31) the odd
// words are all zero; if int32 they are ~2048 random node ids (P(all 0) ~= 0).
__global__ void k_detect(const int* __restrict__ ei32, int e2) {
    int idx = 2 * threadIdx.x + 1;
    for (int k = 0; k < 8; k++, idx += 512)
        if (idx < e2 && idx < 4096 && ei32[idx] != 0) g_is64 = 0;
}

// ---------------- CSR build --------------------------------------------------
__global__ void k_count(const void* __restrict__ ei, int E) {
    int e = blockIdx.x * blockDim.x + threadIdx.x;
    if (e >= E) return;
    int d = (int)idx_at(ei, (long long)E + e);
    atomicAdd(&g_cnt[d], 1);
}

__device__ __forceinline__ int blk_excl_scan(int v, int* warpsum) {
    int tid = threadIdx.x, lane = tid & 31, w = tid >> 5;
    int x = v;
    #pragma unroll
    for (int o = 1; o < 32; o <<= 1) {
        int y = __shfl_up_sync(0xFFFFFFFFu, x, o);
        if (lane >= o) x += y;
    }
    if (lane == 31) warpsum[w] = x;
    __syncthreads();
    if (w == 0 && lane < 8) {
        int s = warpsum[lane];
        #pragma unroll
        for (int o = 1; o < 8; o <<= 1) {
            int y = __shfl_up_sync(0xFFu, s, o);
            if (lane >= o) s += y;
        }
        warpsum[lane] = s;
    }
    __syncthreads();
    return x - v + (w > 0 ? warpsum[w - 1] : 0);
}

__global__ void k_bsum(int n) {
    __shared__ int warpsum[8];
    int i = blockIdx.x * 256 + threadIdx.x;
    int v = (i < n) ? g_cnt[i] : 0;
    int lane = threadIdx.x & 31, w = threadIdx.x >> 5;
    #pragma unroll
    for (int o = 16; o > 0; o >>= 1) v += __shfl_down_sync(0xFFFFFFFFu, v, o);
    if (lane == 0) warpsum[w] = v;
    __syncthreads();
    if (threadIdx.x == 0) {
        int s = 0;
        #pragma unroll
        for (int k = 0; k < 8; k++) s += warpsum[k];
        g_bsum[blockIdx.x] = s;
    }
}

// fused: every block rescans the (<=256) block sums itself, then scans its
// own 256 counts and writes rowptr; re-zeroes cnt (fill cursors).
__global__ void k_rowptr(int nb, int n) {
    __shared__ int ws[8];
    __shared__ int sScan[257];
    int t = threadIdx.x;
    int v = (t < nb) ? g_bsum[t] : 0;
    int ex = blk_excl_scan(v, ws);
    sScan[t] = ex;
    if (t == 255) sScan[256] = ex + v;
    __syncthreads();
    int boff = sScan[blockIdx.x];
    if (blockIdx.x == 0 && t == 0) g_rowptr[n] = sScan[nb];
    __syncthreads();
    int i = blockIdx.x * 256 + t;
    int c = (i < n) ? g_cnt[i] : 0;
    int ex2 = blk_excl_scan(c, ws);
    if (i < n) { g_rowptr[i] = boff + ex2; g_cnt[i] = 0; }
}

__global__ void k_fill(const void* __restrict__ ei, int E) {
    int e = blockIdx.x * blockDim.x + threadIdx.x;
    if (e >= E) return;
    int s = (int)idx_at(ei, e);
    int d = (int)idx_at(ei, (long long)E + e);
    int pos = g_rowptr[d] + atomicAdd(&g_cnt[d], 1);
    g_col[pos] = s;
}

// ---------------- fused prep: blocks [0,384) weights, rest split x ----------
__global__ void k_prep(const float* __restrict__ x, int n4,
                       const float* __restrict__ W0, const float* __restrict__ W1,
                       const float* __restrict__ W2, const float* __restrict__ W3,
                       const float* __restrict__ W4, const float* __restrict__ W5) {
    int b = blockIdx.x;
    if (b < 384) {
        const float* Ws[6] = {W0, W1, W2, W3, W4, W5};
        int m = b >> 6;
        int i = ((b & 63) << 8) + threadIdx.x;   // 0..16383
        int n = i >> 7, k = i & 127;
        float v = Ws[m][k * DIM + n];            // transpose: Wt[n][k]
        bf16 h = __float2bfloat16_rn(v);
        bf16 l = __float2bfloat16_rn(v - __bfloat162float(h));
        g_wtHi[m * DIM * DIM + i] = h;
        g_wtLo[m * DIM * DIM + i] = l;
    } else {
        int i = (b - 384) * 256 + threadIdx.x;
        if (i >= n4) return;
        float4 v = *(const float4*)(x + (size_t)i * 4);
        uint2 hi, lo;
        split2(v.x, v.y, hi.x, lo.x);
        split2(v.z, v.w, hi.y, lo.y);
        *(uint2*)(g_h0Hi + (size_t)i * 4) = hi;
        *(uint2*)(g_h0Lo + (size_t)i * 4) = lo;
        __half2 f0 = __floats2half2_rn(v.x, v.y);
        __half2 f1 = __floats2half2_rn(v.z, v.w);
        *(__half2*)(g_xf + (size_t)i * 4)     = f0;
        *(__half2*)(g_xf + (size_t)i * 4 + 2) = f1;
    }
}

// ---------------- mean aggregation: HALF-warp per node, uint4 fp16 gather ---
// 2 nodes per warp (independent gather chains); each lane loads 16B = 8 cols.
__global__ void k_agg(const __half* __restrict__ h, int N) {
    int w = (blockIdx.x * blockDim.x + threadIdx.x) >> 5;
    int lane = threadIdx.x & 31;
    int node = w * 2 + (lane >> 4);
    int li = lane & 15;
    if (node >= N) return;
    int beg = g_rowptr[node], end = g_rowptr[node + 1];
    float a0 = 0.f, a1 = 0.f, a2 = 0.f, a3 = 0.f;
    float a4 = 0.f, a5 = 0.f, a6 = 0.f, a7 = 0.f;
    const __half* hp = h + li * 8;
    int i = beg;
    for (; i + 1 < end; i += 2) {
        int s0 = __ldg(&g_col[i]), s1 = __ldg(&g_col[i + 1]);
        uint4 v0 = *(const uint4*)(hp + (size_t)s0 * DIM);
        uint4 v1 = *(const uint4*)(hp + (size_t)s1 * DIM);
        float2 p;
        p = __half22float2(*(__half2*)&v0.x); a0 += p.x; a1 += p.y;
        p = __half22float2(*(__half2*)&v0.y); a2 += p.x; a3 += p.y;
        p = __half22float2(*(__half2*)&v0.z); a4 += p.x; a5 += p.y;
        p = __half22float2(*(__half2*)&v0.w); a6 += p.x; a7 += p.y;
        p = __half22float2(*(__half2*)&v1.x); a0 += p.x; a1 += p.y;
        p = __half22float2(*(__half2*)&v1.y); a2 += p.x; a3 += p.y;
        p = __half22float2(*(__half2*)&v1.z); a4 += p.x; a5 += p.y;
        p = __half22float2(*(__half2*)&v1.w); a6 += p.x; a7 += p.y;
    }
    if (i < end) {
        int s0 = __ldg(&g_col[i]);
        uint4 v0 = *(const uint4*)(hp + (size_t)s0 * DIM);
        float2 p;
        p = __half22float2(*(__half2*)&v0.x); a0 += p.x; a1 += p.y;
        p = __half22float2(*(__half2*)&v0.y); a2 += p.x; a3 += p.y;
        p = __half22float2(*(__half2*)&v0.z); a4 += p.x; a5 += p.y;
        p = __half22float2(*(__half2*)&v0.w); a6 += p.x; a7 += p.y;
    }
    int deg = end - beg;
    float inv = 1.0f / (float)(deg > 0 ? deg : 1);
    uint4 hi, lo;
    split2(a0 * inv, a1 * inv, hi.x, lo.x);
    split2(a2 * inv, a3 * inv, hi.y, lo.y);
    split2(a4 * inv, a5 * inv, hi.z, lo.z);
    split2(a6 * inv, a7 * inv, hi.w, lo.w);
    size_t off = (size_t)node * DIM + li * 8;
    *(uint4*)(g_aggHi + off) = hi;
    *(uint4*)(g_aggLo + off) = lo;
}

// ---------------- tensor-core fused dual GEMM (cp.async 2-stage) ------------
// (unchanged from R7 — protected win)
__device__ __forceinline__ void mma_bf16(float* c, const unsigned* a, const unsigned* b) {
    asm volatile(
        "mma.sync.aligned.m16n8k16.row.col.f32.bf16.bf16.f32 "
        "{%0,%1,%2,%3}, {%4,%5,%6,%7}, {%8,%9}, {%0,%1,%2,%3};\n"
        : "+f"(c[0]), "+f"(c[1]), "+f"(c[2]), "+f"(c[3])
        : "r"(a[0]), "r"(a[1]), "r"(a[2]), "r"(a[3]), "r"(b[0]), "r"(b[1]));
}

#define LDW 40                       // bf16 per smem row (80 B)
#define ARR_B (128 * LDW * 2)        // 10240 B per array
#define STG_B (4 * ARR_B)            // 40960 B per stage
#define GSMEM (2 * STG_B)            // 81920 B total

__global__ void __launch_bounds__(256)
k_gemm_tc(const bf16* __restrict__ Ahi, const bf16* __restrict__ Alo,
          const bf16* __restrict__ Hhi, const bf16* __restrict__ Hlo,
          const bf16* __restrict__ WtHi, const bf16* __restrict__ WtLo,
          const float* __restrict__ bias, __half* __restrict__ outF,
          bf16* __restrict__ outHi, bf16* __restrict__ outLo, int M)
{
    extern __shared__ __align__(16) char smem[];
    const uint32_t sb = smem_u32(smem);

    const int tid  = threadIdx.x;
    const int lane = tid & 31, warp = tid >> 5;
    const int wm = warp & 3, wn = warp >> 2;
    const int g  = lane >> 2, t = lane & 3;
    const int row0 = blockIdx.x * 128;

    const int r_ld  = tid >> 2;
    const int k8_ld = (tid & 3) * 8;

    float acc[2][8][4];
    #pragma unroll
    for (int a = 0; a < 2; a++)
        #pragma unroll
        for (int b = 0; b < 8; b++)
            #pragma unroll
            for (int c = 0; c < 4; c++) acc[a][b][c] = 0.f;

    auto issue = [&](int kc, int stg) {
        const bf16* srcHi = (kc < 4) ? Ahi : Hhi;
        const bf16* srcLo = (kc < 4) ? Alo : Hlo;
        const bf16* wHi   = WtHi + ((kc < 4) ? 0 : DIM * DIM);
        const bf16* wLo   = WtLo + ((kc < 4) ? 0 : DIM * DIM);
        const int koff = (kc & 3) * 32;
        const uint32_t base = sb + stg * STG_B;
        #pragma unroll
        for (int j = 0; j < 2; j++) {
            int r = r_ld + j * 64;
            uint32_t d = base + (uint32_t)(r * LDW + k8_ld) * 2;
            size_t ga = (size_t)(row0 + r) * DIM + koff + k8_ld;
            size_t gw = (size_t)r * DIM + koff + k8_ld;
            cpa16(d,             srcHi + ga);
            cpa16(d + ARR_B,     srcLo + ga);
            cpa16(d + 2 * ARR_B, wHi + gw);
            cpa16(d + 3 * ARR_B, wLo + gw);
        }
        cpa_commit();
    };

    issue(0, 0);

    for (int kc = 0; kc < 8; kc++) {
        if (kc + 1 < 8) {
            issue(kc + 1, (kc + 1) & 1);
            cpa_wait<1>();
        } else {
            cpa_wait<0>();
        }
        __syncthreads();

        const char* stgp = smem + (kc & 1) * STG_B;
        const bf16 (*sAhi)[LDW] = (const bf16(*)[LDW])(stgp);
        const bf16 (*sAlo)[LDW] = (const bf16(*)[LDW])(stgp + ARR_B);
        const bf16 (*sWhi)[LDW] = (const bf16(*)[LDW])(stgp + 2 * ARR_B);
        const bf16 (*sWlo)[LDW] = (const bf16(*)[LDW])(stgp + 3 * ARR_B);

        #pragma unroll
        for (int k0 = 0; k0 < 32; k0 += 16) {
            unsigned ahi[2][4], alo[2][4];
            #pragma unroll
            for (int mt = 0; mt < 2; mt++) {
                int rm = wm * 32 + mt * 16;
                ahi[mt][0] = *(const unsigned*)&sAhi[rm + g    ][k0 + 2 * t];
                ahi[mt][1] = *(const unsigned*)&sAhi[rm + 8 + g][k0 + 2 * t];
                ahi[mt][2] = *(const unsigned*)&sAhi[rm + g    ][k0 + 2 * t + 8];
                ahi[mt][3] = *(const unsigned*)&sAhi[rm + 8 + g][k0 + 2 * t + 8];
                alo[mt][0] = *(const unsigned*)&sAlo[rm + g    ][k0 + 2 * t];
                alo[mt][1] = *(const unsigned*)&sAlo[rm + 8 + g][k0 + 2 * t];
                alo[mt][2] = *(const unsigned*)&sAlo[rm + g    ][k0 + 2 * t + 8];
                alo[mt][3] = *(const unsigned*)&sAlo[rm + 8 + g][k0 + 2 * t + 8];
            }
            #pragma unroll
            for (int nt = 0; nt < 8; nt++) {
                int cn = wn * 64 + nt * 8 + g;
                unsigned bhi[2], blo[2];
                bhi[0] = *(const unsigned*)&sWhi[cn][k0 + 2 * t];
                bhi[1] = *(const unsigned*)&sWhi[cn][k0 + 2 * t + 8];
                blo[0] = *(const unsigned*)&sWlo[cn][k0 + 2 * t];
                blo[1] = *(const unsigned*)&sWlo[cn][k0 + 2 * t + 8];
                #pragma unroll
                for (int mt = 0; mt < 2; mt++) {
                    mma_bf16(acc[mt][nt], ahi[mt], bhi);
                    mma_bf16(acc[mt][nt], ahi[mt], blo);
                    mma_bf16(acc[mt][nt], alo[mt], bhi);
                }
            }
        }
        __syncthreads();
    }

    #pragma unroll
    for (int mt = 0; mt < 2; mt++) {
        int r0 = row0 + wm * 32 + mt * 16 + g;
        #pragma unroll
        for (int nt = 0; nt < 8; nt++) {
            int c = wn * 64 + nt * 8 + 2 * t;
            float b0 = __ldg(bias + c), b1 = __ldg(bias + c + 1);
            #pragma unroll
            for (int half = 0; half < 2; half++) {
                int rr = r0 + half * 8;
                if (rr < M) {
                    float ox = fmaxf(acc[mt][nt][2 * half]     + b0, 0.f);
                    float oy = fmaxf(acc[mt][nt][2 * half + 1] + b1, 0.f);
                    size_t off = (size_t)rr * DIM + c;
                    *(__half2*)(outF + off) = __floats2half2_rn(ox, oy);
                    unsigned hi, lo;
                    split2(ox, oy, hi, lo);
                    *(unsigned*)(outHi + off) = hi;
                    *(unsigned*)(outLo + off) = lo;
                }
            }
        }
    }
}

// ---------------- meanmax readout (bounds fused; batch is sorted) -----------
__global__ void k_readout(const void* __restrict__ batch, const __half* __restrict__ h,
                          float* __restrict__ out, int n) {
    __shared__ int sB[2];
    int g = blockIdx.x;
    if (threadIdx.x < 2) {
        long long target = g + threadIdx.x;
        int lo = 0, hi = n;
        while (lo < hi) {
            int mid = (lo + hi) >> 1;
            if (idx_at(batch, mid) < target) lo = mid + 1; else hi = mid;
        }
        sB[threadIdx.x] = lo;
    }
    __syncthreads();
    int s = sB[0], e = sB[1];
    int c = threadIdx.x;                 // 0..127
    float sum = 0.f, mx = 0.f;           // post-relu values >= 0; empty -> 0
    for (int i = s; i < e; i++) {
        float v = __half2float(__ldg(h + (size_t)i * DIM + c));
        sum += v;
        mx = fmaxf(mx, v);
    }
    out[g * (2 * DIM) + c]       = sum / fmaxf((float)(e - s), 1.f);
    out[g * (2 * DIM) + DIM + c] = mx;
}

// ---------------- launcher ---------------------------------------------------
extern "C" void kernel_launch(void* const* d_in, const int* in_sizes, int n_in,
                              void* d_out, int out_size)
{
    const float* x     = (const float*)d_in[0];
    const void*  ei    = d_in[1];
    const void*  batch = d_in[2];
    const float* Wl0 = (const float*)d_in[3];
    const float* bl0 = (const float*)d_in[4];
    const float* Wr0 = (const float*)d_in[5];
    const float* Wl1 = (const float*)d_in[6];
    const float* bl1 = (const float*)d_in[7];
    const float* Wr1 = (const float*)d_in[8];
    const float* Wl2 = (const float*)d_in[9];
    const float* bl2 = (const float*)d_in[10];
    const float* Wr2 = (const float*)d_in[11];
    float* out = (float*)d_out;

    const int N = in_sizes[0] / DIM;     // 50000
    const int E = in_sizes[1] / 2;       // 800000

    __half *xf, *hfA, *hfB;
    bf16 *aggHi, *aggLo, *h0Hi, *h0Lo, *h1Hi, *h1Lo, *h2Hi, *h2Lo, *wtHi, *wtLo;
    cudaGetSymbolAddress((void**)&xf,  g_xf);
    cudaGetSymbolAddress((void**)&hfA, g_hfA);
    cudaGetSymbolAddress((void**)&hfB, g_hfB);
    cudaGetSymbolAddress((void**)&aggHi, g_aggHi);
    cudaGetSymbolAddress((void**)&aggLo, g_aggLo);
    cudaGetSymbolAddress((void**)&h0Hi, g_h0Hi);
    cudaGetSymbolAddress((void**)&h0Lo, g_h0Lo);
    cudaGetSymbolAddress((void**)&h1Hi, g_h1Hi);
    cudaGetSymbolAddress((void**)&h1Lo, g_h1Lo);
    cudaGetSymbolAddress((void**)&h2Hi, g_h2Hi);
    cudaGetSymbolAddress((void**)&h2Lo, g_h2Lo);
    cudaGetSymbolAddress((void**)&wtHi, g_wtHi);
    cudaGetSymbolAddress((void**)&wtLo, g_wtLo);

    cudaFuncSetAttribute(k_gemm_tc, cudaFuncAttributeMaxDynamicSharedMemorySize, GSMEM);

    const int nb = (N + 255) / 256;      // 196

    k_init  <<<(NN + 255) / 256, 256>>>();
    k_detect<<<1, 256>>>((const int*)ei, 2 * E);
    k_count <<<(E + 255) / 256, 256>>>(ei, E);
    k_bsum  <<<nb, 256>>>(N);
    k_rowptr<<<nb, 256>>>(nb, N);
    k_fill  <<<(E + 255) / 256, 256>>>(ei, E);

    k_prep  <<<384 + (N * 32 + 255) / 256, 256>>>(x, N * 32,
                                                  Wl0, Wr0, Wl1, Wr1, Wl2, Wr2);

    const int aggWarps = (N + 1) / 2;
    const int aggGrid  = (aggWarps * 32 + 255) / 256;
    const int gemmGrid = (N + 127) / 128;

    // layer 0
    k_agg    <<<aggGrid, 256>>>(xf, N);
    k_gemm_tc<<<gemmGrid, 256, GSMEM>>>(aggHi, aggLo, h0Hi, h0Lo,
                                        wtHi + 0 * DIM * DIM, wtLo + 0 * DIM * DIM,
                                        bl0, hfA, h1Hi, h1Lo, N);
    // layer 1
    k_agg    <<<aggGrid, 256>>>(hfA, N);
    k_gemm_tc<<<gemmGrid, 256, GSMEM>>>(aggHi, aggLo, h1Hi, h1Lo,
                                        wtHi + 2 * DIM * DIM, wtLo + 2 * DIM * DIM,
                                        bl1, hfB, h2Hi, h2Lo, N);
    // layer 2
    k_agg    <<<aggGrid, 256>>>(hfB, N);
    k_gemm_tc<<<gemmGrid, 256, GSMEM>>>(aggHi, aggLo, h2Hi, h2Lo,
                                        wtHi + 4 * DIM * DIM, wtLo + 4 * DIM * DIM,
                                        bl2, hfA, h1Hi, h1Lo, N);

    k_readout<<<NG, DIM>>>(batch, hfA, out, N);
}

// round 9
// speedup vs baseline: 1.9820x; 1.5122x over previous
#include <cuda_runtime.h>
#include <cuda_bf16.h>
#include <cuda_fp16.h>
#include <stdint.h>

#define NN 50000
#define NNP 50048              // padded to 391*128 (GEMM tile rows)
#define NG 256
#define DIM 128
#define NE 800000

// ---------------- scratch (static __device__ => no runtime allocation) ------
// all fp16, padded; padding rows are never written => stay zero (static init)
__device__ __half g_xf  [NNP * DIM];
__device__ __half g_hfA [NNP * DIM];
__device__ __half g_hfB [NNP * DIM];
__device__ __half g_aggF[NNP * DIM];
__device__ __half g_wtF [6 * DIM * DIM];     // transposed [n][k], fp16
__device__ int   g_rowptr[NN + 1];
__device__ int   g_cnt[NN];
__device__ int   g_col[NE];
__device__ int   g_is64;
__device__ int   g_bsum[256];

// ---------------- helpers ----------------------------------------------------
__device__ __forceinline__ long long idx_at(const void* p, long long i) {
    if (g_is64) return ((const long long*)p)[i];
    return (long long)((const int*)p)[i];
}

__device__ __forceinline__ uint32_t smem_u32(const void* p) {
    uint32_t a;
    asm("{ .reg .u64 t; cvta.to.shared.u64 t, %1; cvt.u32.u64 %0, t; }" : "=r"(a) : "l"(p));
    return a;
}

__device__ __forceinline__ void cpa16(uint32_t dst, const void* src) {
    asm volatile("cp.async.ca.shared.global [%0], [%1], 16;" :: "r"(dst), "l"(src) : "memory");
}
__device__ __forceinline__ void cpa_commit() {
    asm volatile("cp.async.commit_group;" ::: "memory");
}
template <int N_>
__device__ __forceinline__ void cpa_wait() {
    asm volatile("cp.async.wait_group %0;" :: "n"(N_) : "memory");
}

// ---------------- init / detect ----------------------------------------------
__global__ void k_init() {
    int i = blockIdx.x * blockDim.x + threadIdx.x;
    if (i < NN) g_cnt[i] = 0;
    if (i == 0) g_is64 = 1;
}

// Sample first 4096 32-bit words. If edges are int64 (nonneg < 2^31) the odd
// words are all zero; if int32 they are ~2048 random node ids (P(all 0) ~= 0).
__global__ void k_detect(const int* __restrict__ ei32, int e2) {
    int idx = 2 * threadIdx.x + 1;
    for (int k = 0; k < 8; k++, idx += 512)
        if (idx < e2 && idx < 4096 && ei32[idx] != 0) g_is64 = 0;
}

// ---------------- CSR build --------------------------------------------------
__global__ void k_count(const void* __restrict__ ei, int E) {
    int e = blockIdx.x * blockDim.x + threadIdx.x;
    if (e >= E) return;
    int d = (int)idx_at(ei, (long long)E + e);
    atomicAdd(&g_cnt[d], 1);
}

__device__ __forceinline__ int blk_excl_scan(int v, int* warpsum) {
    int tid = threadIdx.x, lane = tid & 31, w = tid >> 5;
    int x = v;
    #pragma unroll
    for (int o = 1; o < 32; o <<= 1) {
        int y = __shfl_up_sync(0xFFFFFFFFu, x, o);
        if (lane >= o) x += y;
    }
    if (lane == 31) warpsum[w] = x;
    __syncthreads();
    if (w == 0 && lane < 8) {
        int s = warpsum[lane];
        #pragma unroll
        for (int o = 1; o < 8; o <<= 1) {
            int y = __shfl_up_sync(0xFFu, s, o);
            if (lane >= o) s += y;
        }
        warpsum[lane] = s;
    }
    __syncthreads();
    return x - v + (w > 0 ? warpsum[w - 1] : 0);
}

__global__ void k_bsum(int n) {
    __shared__ int warpsum[8];
    int i = blockIdx.x * 256 + threadIdx.x;
    int v = (i < n) ? g_cnt[i] : 0;
    int lane = threadIdx.x & 31, w = threadIdx.x >> 5;
    #pragma unroll
    for (int o = 16; o > 0; o >>= 1) v += __shfl_down_sync(0xFFFFFFFFu, v, o);
    if (lane == 0) warpsum[w] = v;
    __syncthreads();
    if (threadIdx.x == 0) {
        int s = 0;
        #pragma unroll
        for (int k = 0; k < 8; k++) s += warpsum[k];
        g_bsum[blockIdx.x] = s;
    }
}

// fused: every block rescans the (<=256) block sums itself, then scans its
// own 256 counts and writes rowptr; re-zeroes cnt (fill cursors).
__global__ void k_rowptr(int nb, int n) {
    __shared__ int ws[8];
    __shared__ int sScan[257];
    int t = threadIdx.x;
    int v = (t < nb) ? g_bsum[t] : 0;
    int ex = blk_excl_scan(v, ws);
    sScan[t] = ex;
    if (t == 255) sScan[256] = ex + v;
    __syncthreads();
    int boff = sScan[blockIdx.x];
    if (blockIdx.x == 0 && t == 0) g_rowptr[n] = sScan[nb];
    __syncthreads();
    int i = blockIdx.x * 256 + t;
    int c = (i < n) ? g_cnt[i] : 0;
    int ex2 = blk_excl_scan(c, ws);
    if (i < n) { g_rowptr[i] = boff + ex2; g_cnt[i] = 0; }
}

__global__ void k_fill(const void* __restrict__ ei, int E) {
    int e = blockIdx.x * blockDim.x + threadIdx.x;
    if (e >= E) return;
    int s = (int)idx_at(ei, e);
    int d = (int)idx_at(ei, (long long)E + e);
    int pos = g_rowptr[d] + atomicAdd(&g_cnt[d], 1);
    g_col[pos] = s;
}

// ---------------- fused prep: blocks [0,96) weights, rest x -> fp16 ---------
__global__ void k_prep(const float* __restrict__ x, int n4,
                       const float* __restrict__ W0, const float* __restrict__ W1,
                       const float* __restrict__ W2, const float* __restrict__ W3,
                       const float* __restrict__ W4, const float* __restrict__ W5) {
    int b = blockIdx.x;
    if (b < 96) {
        // 6 matrices x 16384 elems / (256 thr * 4096/256...): 96 blocks x 1024 elems
        const float* Ws[6] = {W0, W1, W2, W3, W4, W5};
        int m = b >> 4;                           // 16 blocks per matrix
        int base = (b & 15) * 1024;
        for (int q = 0; q < 4; q++) {
            int i = base + q * 256 + threadIdx.x; // 0..16383
            int n = i >> 7, k = i & 127;
            g_wtF[m * DIM * DIM + i] = __float2half_rn(Ws[m][k * DIM + n]);
        }
    } else {
        int i = (b - 96) * 256 + threadIdx.x;
        if (i >= n4) return;
        float4 v = *(const float4*)(x + (size_t)i * 4);
        *(__half2*)(g_xf + (size_t)i * 4)     = __floats2half2_rn(v.x, v.y);
        *(__half2*)(g_xf + (size_t)i * 4 + 2) = __floats2half2_rn(v.z, v.w);
    }
}

// ---------------- mean aggregation: half-warp per node, uint4 fp16 gather ---
__global__ void k_agg(const __half* __restrict__ h, int N) {
    int w = (blockIdx.x * blockDim.x + threadIdx.x) >> 5;
    int lane = threadIdx.x & 31;
    int node = w * 2 + (lane >> 4);
    int li = lane & 15;
    if (node >= N) return;
    int beg = g_rowptr[node], end = g_rowptr[node + 1];
    float a0 = 0.f, a1 = 0.f, a2 = 0.f, a3 = 0.f;
    float a4 = 0.f, a5 = 0.f, a6 = 0.f, a7 = 0.f;
    const __half* hp = h + li * 8;
    int i = beg;
    for (; i + 1 < end; i += 2) {
        int s0 = __ldg(&g_col[i]), s1 = __ldg(&g_col[i + 1]);
        uint4 v0 = *(const uint4*)(hp + (size_t)s0 * DIM);
        uint4 v1 = *(const uint4*)(hp + (size_t)s1 * DIM);
        float2 p;
        p = __half22float2(*(__half2*)&v0.x); a0 += p.x; a1 += p.y;
        p = __half22float2(*(__half2*)&v0.y); a2 += p.x; a3 += p.y;
        p = __half22float2(*(__half2*)&v0.z); a4 += p.x; a5 += p.y;
        p = __half22float2(*(__half2*)&v0.w); a6 += p.x; a7 += p.y;
        p = __half22float2(*(__half2*)&v1.x); a0 += p.x; a1 += p.y;
        p = __half22float2(*(__half2*)&v1.y); a2 += p.x; a3 += p.y;
        p = __half22float2(*(__half2*)&v1.z); a4 += p.x; a5 += p.y;
        p = __half22float2(*(__half2*)&v1.w); a6 += p.x; a7 += p.y;
    }
    if (i < end) {
        int s0 = __ldg(&g_col[i]);
        uint4 v0 = *(const uint4*)(hp + (size_t)s0 * DIM);
        float2 p;
        p = __half22float2(*(__half2*)&v0.x); a0 += p.x; a1 += p.y;
        p = __half22float2(*(__half2*)&v0.y); a2 += p.x; a3 += p.y;
        p = __half22float2(*(__half2*)&v0.z); a4 += p.x; a5 += p.y;
        p = __half22float2(*(__half2*)&v0.w); a6 += p.x; a7 += p.y;
    }
    int deg = end - beg;
    float inv = 1.0f / (float)(deg > 0 ? deg : 1);
    uint4 o;
    *(__half2*)&o.x = __floats2half2_rn(a0 * inv, a1 * inv);
    *(__half2*)&o.y = __floats2half2_rn(a2 * inv, a3 * inv);
    *(__half2*)&o.z = __floats2half2_rn(a4 * inv, a5 * inv);
    *(__half2*)&o.w = __floats2half2_rn(a6 * inv, a7 * inv);
    *(uint4*)(g_aggF + (size_t)node * DIM + li * 8) = o;
}

// ---------------- tensor-core fused dual GEMM (fp16 single product) ---------
// out = relu(A@Wl + H@Wr + bias); all operands fp16, fp32 accumulate.
// BM=128, BN=128; 8 chunks of BK=32 (0-3: A/Wl, 4-7: H/Wr). 8 warps (4x2).
// cp.async 2-stage pipeline; smem rows 40 halfs (80B), conflict-free frags.
__device__ __forceinline__ void mma_f16(float* c, const unsigned* a, const unsigned* b) {
    asm volatile(
        "mma.sync.aligned.m16n8k16.row.col.f32.f16.f16.f32 "
        "{%0,%1,%2,%3}, {%4,%5,%6,%7}, {%8,%9}, {%0,%1,%2,%3};\n"
        : "+f"(c[0]), "+f"(c[1]), "+f"(c[2]), "+f"(c[3])
        : "r"(a[0]), "r"(a[1]), "r"(a[2]), "r"(a[3]), "r"(b[0]), "r"(b[1]));
}

#define LDW 40                       // halfs per smem row (80 B)
#define ARR_B (128 * LDW * 2)        // 10240 B per array
#define STG_B (2 * ARR_B)            // 20480 B per stage (A + W)
#define GSMEM (2 * STG_B)            // 40960 B total

__global__ void __launch_bounds__(256)
k_gemm_tc(const __half* __restrict__ Af, const __half* __restrict__ Hf,
          const __half* __restrict__ Wf, const float* __restrict__ bias,
          __half* __restrict__ outF, int M)
{
    extern __shared__ __align__(16) char smem[];
    const uint32_t sb = smem_u32(smem);

    const int tid  = threadIdx.x;
    const int lane = tid & 31, warp = tid >> 5;
    const int wm = warp & 3, wn = warp >> 2;
    const int g  = lane >> 2, t = lane & 3;
    const int row0 = blockIdx.x * 128;

    const int r_ld  = tid >> 2;          // rows 0..63 (+64)
    const int k8_ld = (tid & 3) * 8;     // k offset 0/8/16/24

    float acc[2][8][4];
    #pragma unroll
    for (int a = 0; a < 2; a++)
        #pragma unroll
        for (int b = 0; b < 8; b++)
            #pragma unroll
            for (int c = 0; c < 4; c++) acc[a][b][c] = 0.f;

    auto issue = [&](int kc, int stg) {
        const __half* src = (kc < 4) ? Af : Hf;
        const __half* w   = Wf + ((kc < 4) ? 0 : DIM * DIM);
        const int koff = (kc & 3) * 32;
        const uint32_t base = sb + stg * STG_B;
        #pragma unroll
        for (int j = 0; j < 2; j++) {
            int r = r_ld + j * 64;
            uint32_t d = base + (uint32_t)(r * LDW + k8_ld) * 2;
            size_t ga = (size_t)(row0 + r) * DIM + koff + k8_ld;  // padded, in-bounds
            size_t gw = (size_t)r * DIM + koff + k8_ld;
            cpa16(d,         src + ga);
            cpa16(d + ARR_B, w + gw);
        }
        cpa_commit();
    };

    issue(0, 0);

    for (int kc = 0; kc < 8; kc++) {
        if (kc + 1 < 8) {
            issue(kc + 1, (kc + 1) & 1);
            cpa_wait<1>();
        } else {
            cpa_wait<0>();
        }
        __syncthreads();

        const char* stgp = smem + (kc & 1) * STG_B;
        const __half (*sA)[LDW] = (const __half(*)[LDW])(stgp);
        const __half (*sW)[LDW] = (const __half(*)[LDW])(stgp + ARR_B);

        #pragma unroll
        for (int k0 = 0; k0 < 32; k0 += 16) {
            unsigned af[2][4];
            #pragma unroll
            for (int mt = 0; mt < 2; mt++) {
                int rm = wm * 32 + mt * 16;
                af[mt][0] = *(const unsigned*)&sA[rm + g    ][k0 + 2 * t];
                af[mt][1] = *(const unsigned*)&sA[rm + 8 + g][k0 + 2 * t];
                af[mt][2] = *(const unsigned*)&sA[rm + g    ][k0 + 2 * t + 8];
                af[mt][3] = *(const unsigned*)&sA[rm + 8 + g][k0 + 2 * t + 8];
            }
            #pragma unroll
            for (int nt = 0; nt < 8; nt++) {
                int cn = wn * 64 + nt * 8 + g;
                unsigned bf[2];
                bf[0] = *(const unsigned*)&sW[cn][k0 + 2 * t];
                bf[1] = *(const unsigned*)&sW[cn][k0 + 2 * t + 8];
                #pragma unroll
                for (int mt = 0; mt < 2; mt++)
                    mma_f16(acc[mt][nt], af[mt], bf);
            }
        }
        __syncthreads();
    }

    // epilogue: + bias, relu; store fp16 only
    #pragma unroll
    for (int mt = 0; mt < 2; mt++) {
        int r0 = row0 + wm * 32 + mt * 16 + g;
        #pragma unroll
        for (int nt = 0; nt < 8; nt++) {
            int c = wn * 64 + nt * 8 + 2 * t;
            float b0 = __ldg(bias + c), b1 = __ldg(bias + c + 1);
            #pragma unroll
            for (int half = 0; half < 2; half++) {
                int rr = r0 + half * 8;
                if (rr < M) {
                    float ox = fmaxf(acc[mt][nt][2 * half]     + b0, 0.f);
                    float oy = fmaxf(acc[mt][nt][2 * half + 1] + b1, 0.f);
                    *(__half2*)(outF + (size_t)rr * DIM + c) = __floats2half2_rn(ox, oy);
                }
            }
        }
    }
}

// ---------------- meanmax readout (bounds fused; batch is sorted) -----------
__global__ void k_readout(const void* __restrict__ batch, const __half* __restrict__ h,
                          float* __restrict__ out, int n) {
    __shared__ int sB[2];
    int g = blockIdx.x;
    if (threadIdx.x < 2) {
        long long target = g + threadIdx.x;
        int lo = 0, hi = n;
        while (lo < hi) {
            int mid = (lo + hi) >> 1;
            if (idx_at(batch, mid) < target) lo = mid + 1; else hi = mid;
        }
        sB[threadIdx.x] = lo;
    }
    __syncthreads();
    int s = sB[0], e = sB[1];
    int c = threadIdx.x;                 // 0..127
    float sum = 0.f, mx = 0.f;           // post-relu values >= 0; empty -> 0
    for (int i = s; i < e; i++) {
        float v = __half2float(__ldg(h + (size_t)i * DIM + c));
        sum += v;
        mx = fmaxf(mx, v);
    }
    out[g * (2 * DIM) + c]       = sum / fmaxf((float)(e - s), 1.f);
    out[g * (2 * DIM) + DIM + c] = mx;
}

// ---------------- launcher ---------------------------------------------------
extern "C" void kernel_launch(void* const* d_in, const int* in_sizes, int n_in,
                              void* d_out, int out_size)
{
    const float* x     = (const float*)d_in[0];
    const void*  ei    = d_in[1];
    const void*  batch = d_in[2];
    const float* Wl0 = (const float*)d_in[3];
    const float* bl0 = (const float*)d_in[4];
    const float* Wr0 = (const float*)d_in[5];
    const float* Wl1 = (const float*)d_in[6];
    const float* bl1 = (const float*)d_in[7];
    const float* Wr1 = (const float*)d_in[8];
    const float* Wl2 = (const float*)d_in[9];
    const float* bl2 = (const float*)d_in[10];
    const float* Wr2 = (const float*)d_in[11];
    float* out = (float*)d_out;

    const int N = in_sizes[0] / DIM;     // 50000
    const int E = in_sizes[1] / 2;       // 800000

    __half *xf, *hfA, *hfB, *aggF, *wtF;
    cudaGetSymbolAddress((void**)&xf,   g_xf);
    cudaGetSymbolAddress((void**)&hfA,  g_hfA);
    cudaGetSymbolAddress((void**)&hfB,  g_hfB);
    cudaGetSymbolAddress((void**)&aggF, g_aggF);
    cudaGetSymbolAddress((void**)&wtF,  g_wtF);

    cudaFuncSetAttribute(k_gemm_tc, cudaFuncAttributeMaxDynamicSharedMemorySize, GSMEM);

    const int nb = (N + 255) / 256;      // 196

    k_init  <<<(NN + 255) / 256, 256>>>();
    k_detect<<<1, 256>>>((const int*)ei, 2 * E);
    k_count <<<(E + 255) / 256, 256>>>(ei, E);
    k_bsum  <<<nb, 256>>>(N);
    k_rowptr<<<nb, 256>>>(nb, N);
    k_fill  <<<(E + 255) / 256, 256>>>(ei, E);

    k_prep  <<<96 + (N * 32 + 255) / 256, 256>>>(x, N * 32,
                                                 Wl0, Wr0, Wl1, Wr1, Wl2, Wr2);

    const int aggWarps = (N + 1) / 2;
    const int aggGrid  = (aggWarps * 32 + 255) / 256;
    const int gemmGrid = (N + 127) / 128;

    // layer 0
    k_agg    <<<aggGrid, 256>>>(xf, N);
    k_gemm_tc<<<gemmGrid, 256, GSMEM>>>(aggF, xf, wtF + 0 * DIM * DIM, bl0, hfA, N);
    // layer 1
    k_agg    <<<aggGrid, 256>>>(hfA, N);
    k_gemm_tc<<<gemmGrid, 256, GSMEM>>>(aggF, hfA, wtF + 2 * DIM * DIM, bl1, hfB, N);
    // layer 2
    k_agg    <<<aggGrid, 256>>>(hfB, N);
    k_gemm_tc<<<gemmGrid, 256, GSMEM>>>(aggF, hfB, wtF + 4 * DIM * DIM, bl2, hfA, N);

    k_readout<<<NG, DIM>>>(batch, hfA, out, N);
}